// round 10
// baseline (speedup 1.0000x reference)
#include <cuda_runtime.h>

#define BB 128
#define TT 1000
#define NN 1024
#define ALPHA_C 0.995f
#define VTH_C 2.0f

#define SCB 4                 // scan blocks
#define CPB (BB / SCB)        // chains per scan block = 32
#define CHUNK 50              // timesteps per chunk
#define NCHUNK (TT / CHUNK)   // 20
#define PAD (CHUNK + 1)       // conflict-free staging stride
#define GEMV_BLOCKS 440
#define TOTAL_BLOCKS (GEMV_BLOCKS + SCB)   // 444 = 3/SM * 148 SM, one wave
#define GRP 10                              // rows per producer step; 10|50, 10|1000

// drive scratch, block-major: [SCB][TT][CPB]
__device__ float g_drive[SCB * TT * CPB];
// produced-count per (scan block, chunk); zero at load, re-zeroed by consumer
__device__ unsigned g_ctr[SCB * NCHUNK];

// ---------------------------------------------------------------------------
// sync / copy helpers
// ---------------------------------------------------------------------------
__device__ __forceinline__ void red_release_add(unsigned* p, unsigned v) {
    asm volatile("red.release.gpu.global.add.u32 [%0], %1;"
                 :: "l"(p), "r"(v) : "memory");
}
__device__ __forceinline__ unsigned ld_acquire(const unsigned* p) {
    unsigned v;
    asm volatile("ld.acquire.gpu.global.u32 %0, [%1];"
                 : "=r"(v) : "l"(p) : "memory");
    return v;
}
__device__ __forceinline__ void st_relaxed(unsigned* p, unsigned v) {
    asm volatile("st.relaxed.gpu.global.u32 [%0], %1;"
                 :: "l"(p), "r"(v) : "memory");
}
__device__ __forceinline__ void cp_async16(void* smem_dst, const void* gmem_src) {
    unsigned saddr = (unsigned)__cvta_generic_to_shared(smem_dst);
    asm volatile("cp.async.ca.shared.global [%0], [%1], 16;\n"
                 :: "r"(saddr), "l"(gmem_src) : "memory");
}
__device__ __forceinline__ void cp_async_commit() {
    asm volatile("cp.async.commit_group;\n" ::: "memory");
}
template <int N>
__device__ __forceinline__ void cp_async_wait() {
    asm volatile("cp.async.wait_group %0;\n" :: "n"(N) : "memory");
}

// ---------------------------------------------------------------------------
// producer: drive[b,t] = dot(x[b,t,:], w), warp per row, 10 rows per step.
// Natural b-major sweep (max DRAM stream locality, R1-proven). w in regs,
// x front-batched MLP=8 (needs ~80 regs -> 3 blocks/SM). One release-atomic
// per 10-row group; groups never straddle a (blk, chunk) cell.
// ---------------------------------------------------------------------------
__device__ void gemv_part(const float* __restrict__ x, const float* __restrict__ w) {
    const int lane  = threadIdx.x & 31;
    const int warp  = ((blockIdx.x - SCB) * blockDim.x + threadIdx.x) >> 5;
    const int nwarp = (GEMV_BLOCKS * 256) >> 5;     // 3520

    const float4* __restrict__ w4 = (const float4*)w;
    float4 wr[8];
#pragma unroll
    for (int k = 0; k < 8; k++) wr[k] = w4[lane + 32 * k];

    const int G = (BB * TT) / GRP;                   // 12800 groups
    for (int g = warp; g < G; g += nwarp) {
        const int q0    = g * GRP;                   // b-major row index
        const int b     = q0 / TT;
        const int t0    = q0 - b * TT;               // multiple of 10
        const int chunk = t0 / CHUNK;                // same for whole group
        const int blk   = b >> 5;

        const float4* __restrict__ x4 =
            (const float4*)(x + (size_t)q0 * NN);    // 10 consecutive rows

#pragma unroll
        for (int r = 0; r < GRP; r++) {
            float4 xv[8];
#pragma unroll
            for (int k = 0; k < 8; k++)              // front-batched: MLP = 8
                xv[k] = x4[r * (NN / 4) + lane + 32 * k];

            float s = 0.0f;
#pragma unroll
            for (int k = 0; k < 8; k++) {
                s += xv[k].x * wr[k].x;
                s += xv[k].y * wr[k].y;
                s += xv[k].z * wr[k].z;
                s += xv[k].w * wr[k].w;
            }
#pragma unroll
            for (int off = 16; off > 0; off >>= 1)
                s += __shfl_xor_sync(0xffffffffu, s, off);
            if (lane == 0)
                g_drive[blk * (TT * CPB) + (t0 + r) * CPB + (b & 31)] = s;
        }
        if (lane == 0)
            red_release_add(&g_ctr[blk * NCHUNK + chunk], GRP);
    }
}

// ---------------------------------------------------------------------------
// consumer: LIF scan for 32 chains; tracks producer chunk-by-chunk.
// ---------------------------------------------------------------------------
__device__ void scan_part(int blk, float* __restrict__ out) {
    __shared__ float sd[2][CHUNK * CPB];   // drive staging [t][chain]
    __shared__ float sv[CPB * PAD];        // v staging [chain][t]

    const int tid = threadIdx.x;           // 0..255
    const int b0  = blk * CPB;
    const float4* __restrict__ gsrc =
        (const float4*)(g_drive + (size_t)blk * TT * CPB);
    const int F4C = CHUNK * CPB / 4;       // 400 float4 per chunk
    const unsigned FULL = (unsigned)(CHUNK * CPB);

    while (ld_acquire(&g_ctr[blk * NCHUNK + 0]) < FULL) __nanosleep(64);
#pragma unroll
    for (int k = 0; k < 2; k++) {
        int idx = tid + 256 * k;
        if (idx < F4C) cp_async16(&((float4*)sd[0])[idx], &gsrc[idx]);
    }
    cp_async_commit();

    float v = 0.0f;
    bool  p = false;

    for (int c = 0; c < NCHUNK; c++) {
        if (c + 1 < NCHUNK) {
            while (ld_acquire(&g_ctr[blk * NCHUNK + c + 1]) < FULL) __nanosleep(64);
            const float4* src = gsrc + (c + 1) * F4C;
            float4* dst = (float4*)sd[(c + 1) & 1];
#pragma unroll
            for (int k = 0; k < 2; k++) {
                int idx = tid + 256 * k;
                if (idx < F4C) cp_async16(&dst[idx], &src[idx]);
            }
            cp_async_commit();
            cp_async_wait<1>();   // chunk c's group complete
        } else {
            cp_async_wait<0>();
        }
        __syncthreads();          // all threads passed waits for chunks c, c+1

        if (tid == 0) st_relaxed(&g_ctr[blk * NCHUNK + c], 0u);  // replay-safe

        if (tid < CPB) {
            const float* __restrict__ d = sd[c & 1];
#pragma unroll
            for (int i = 0; i < CHUNK; i++) {
                float dd = d[i * CPB + tid];        // off-chain LDS
                float w1 = dd - VTH_C;              // off-chain
                v = fmaf(ALPHA_C, v, p ? w1 : dd);  // FSEL + FFMA on chain
                p = (v > VTH_C);                    // FSETP on chain
                sv[tid * PAD + i] = v;              // z recomputed by writers
            }
        }
        __syncthreads();

        const int tbase = c * CHUNK;
        float* __restrict__ vo = out + (size_t)b0 * TT + tbase;
        float* __restrict__ zo = vo + (size_t)BB * TT;
#pragma unroll
        for (int k = 0; k < 7; k++) {
            int idx = tid + 256 * k;        // 0..1599
            if (idx < CHUNK * CPB) {
                int bb = idx / CHUNK;
                int ii = idx - bb * CHUNK;
                float vv = sv[bb * PAD + ii];
                vo[(size_t)bb * TT + ii] = vv;
                zo[(size_t)bb * TT + ii] = (vv > VTH_C) ? 1.0f : 0.0f;
            }
        }
    }
}

// ---------------------------------------------------------------------------
// fused kernel: blocks [0,SCB) consume, blocks [SCB, TOTAL) produce
// 3 blocks/SM (~80-reg budget -> full MLP-8 with w in regs), one wave.
// ---------------------------------------------------------------------------
__global__ void __launch_bounds__(256, 3) lif_fused_kernel(
    const float* __restrict__ x, const float* __restrict__ w,
    float* __restrict__ out) {
    if (blockIdx.x < SCB) {
        scan_part(blockIdx.x, out);
    } else {
        gemv_part(x, w);
    }
}

extern "C" void kernel_launch(void* const* d_in, const int* in_sizes, int n_in,
                              void* d_out, int out_size) {
    const float* x = (const float*)d_in[0];   // [B, T, N] f32
    const float* w = (const float*)d_in[1];   // [N] f32
    float* out = (float*)d_out;               // [2, B, T] f32 (v then z)

    lif_fused_kernel<<<TOTAL_BLOCKS, 256>>>(x, w, out);
}

// round 11
// speedup vs baseline: 1.3932x; 1.3932x over previous
#include <cuda_runtime.h>
#include <cstdint>

#define BB 128
#define TT 1000
#define NN 1024
#define ALPHA_C 0.995f
#define VTH_C 2.0f

#define SCB 4                 // scan blocks
#define CPB (BB / SCB)        // chains per scan block = 32
#define CHUNK 50              // timesteps per chunk
#define NCHUNK (TT / CHUNK)   // 20
#define PAD (CHUNK + 1)       // conflict-free staging stride
#define GEMV_BLOCKS 440
#define TOTAL_BLOCKS (GEMV_BLOCKS + SCB)   // 444 = 3/SM * 148 SM, one wave
#define ROWS_PER_CHUNK (BB * CHUNK)        // 6400
#define GRP 4                               // rows per producer step (R7 core)

#define POISON 0x7FBFFFFFu    // NaN bit pattern; drive values are always finite

// drive scratch, block-major: [SCB][TT][CPB]; poisoned before each run
__device__ float g_drive[SCB * TT * CPB];

// ---------------------------------------------------------------------------
// helpers
// ---------------------------------------------------------------------------
__device__ __forceinline__ void stg_cg(float* p, float v) {
    asm volatile("st.global.cg.f32 [%0], %1;" :: "l"(p), "f"(v) : "memory");
}
// L2-direct async copy: never allocates in L1 -> retry loop always sees fresh L2
__device__ __forceinline__ void cp_async16_cg(void* smem_dst, const void* gmem_src) {
    unsigned saddr = (unsigned)__cvta_generic_to_shared(smem_dst);
    asm volatile("cp.async.cg.shared.global [%0], [%1], 16;\n"
                 :: "r"(saddr), "l"(gmem_src) : "memory");
}
__device__ __forceinline__ void cp_async_commit() {
    asm volatile("cp.async.commit_group;\n" ::: "memory");
}
__device__ __forceinline__ void cp_async_wait0() {
    asm volatile("cp.async.wait_group 0;\n" ::: "memory");
}

// ---------------------------------------------------------------------------
// Kernel 0: poison the drive buffer (every call; ~0.5 MB)
// ---------------------------------------------------------------------------
__global__ void lif_poison_kernel() {
    int i = blockIdx.x * 256 + threadIdx.x;          // 32000 uint4
    ((uint4*)g_drive)[i] = make_uint4(POISON, POISON, POISON, POISON);
}

// ---------------------------------------------------------------------------
// producer: drive[b,t] = dot(x[b,t,:], w)  — R7 core, ZERO sync overhead.
// Chunk-outer order (pacing), 4 consecutive t per group, w in regs, MLP=8.
// ---------------------------------------------------------------------------
__device__ void gemv_part(const float* __restrict__ x, const float* __restrict__ w) {
    const int lane  = threadIdx.x & 31;
    const int warp  = ((blockIdx.x - SCB) * blockDim.x + threadIdx.x) >> 5;
    const int nwarp = (GEMV_BLOCKS * 256) >> 5;     // 3520

    const float4* __restrict__ w4 = (const float4*)w;
    float4 wr[8];
#pragma unroll
    for (int k = 0; k < 8; k++) wr[k] = w4[lane + 32 * k];

    const int G = (BB * TT) / GRP;                   // 32000 groups
    for (int g = warp; g < G; g += nwarp) {
        const int q0    = g * GRP;
        const int chunk = q0 / ROWS_PER_CHUNK;
        const int rem0  = q0 - chunk * ROWS_PER_CHUNK;
        const int blk   = rem0 / (CPB * CHUNK);

#pragma unroll
        for (int r = 0; r < GRP; r++) {
            const int rem = rem0 + r;
            const int b   = rem / CHUNK;
            const int t   = chunk * CHUNK + (rem - b * CHUNK);

            const float4* __restrict__ x4 =
                (const float4*)(x + ((size_t)b * TT + t) * NN);
            float s = 0.0f;
#pragma unroll
            for (int k = 0; k < 8; k++) {            // 8 independent LDG.128
                float4 xv = x4[lane + 32 * k];
                s += xv.x * wr[k].x;
                s += xv.y * wr[k].y;
                s += xv.z * wr[k].z;
                s += xv.w * wr[k].w;
            }
#pragma unroll
            for (int off = 16; off > 0; off >>= 1)
                s += __shfl_xor_sync(0xffffffffu, s, off);
            if (lane == 0)
                stg_cg(&g_drive[blk * (TT * CPB) + t * CPB + (b & 31)], s);
        }
    }
}

// ---------------------------------------------------------------------------
// consumer: LIF scan for 32 chains. Completeness detected from the data:
// fetch chunk via cp.async.cg, verify no POISON words remain, else retry.
// No fences anywhere; 32-bit aligned stores are torn-free.
// ---------------------------------------------------------------------------
__device__ void scan_part(int blk, float* __restrict__ out) {
    __shared__ float sd[CHUNK * CPB];      // drive staging [t][chain], 6.4 KB
    __shared__ float sv[CPB * PAD];        // v staging [chain][t]

    const int tid = threadIdx.x;           // 0..255
    const int b0  = blk * CPB;
    const float4* __restrict__ gsrc =
        (const float4*)(g_drive + (size_t)blk * TT * CPB);
    const int F4C = CHUNK * CPB / 4;       // 400 float4 per chunk

    float v = 0.0f;
    bool  p = false;

    for (int c = 0; c < NCHUNK; c++) {
        // ---- fetch + verify (retry until producer filled this chunk) ----
        const float4* src = gsrc + c * F4C;
        int done = 0;
        while (!done) {
#pragma unroll
            for (int k = 0; k < 2; k++) {
                int idx = tid + 256 * k;
                if (idx < F4C) cp_async16_cg(&((float4*)sd)[idx], &src[idx]);
            }
            cp_async_commit();
            cp_async_wait0();
            __syncthreads();               // staged data visible to all
            bool ok = true;
#pragma unroll
            for (int k = 0; k < 2; k++) {
                int idx = tid + 256 * k;
                if (idx < F4C) {
                    uint4 u = ((uint4*)sd)[idx];
                    ok &= (u.x != POISON) & (u.y != POISON) &
                          (u.z != POISON) & (u.w != POISON);
                }
            }
            done = __syncthreads_and(ok);
            if (!done) __nanosleep(128);
        }

        // ---- serial chains (warp 0; one chain per thread) ----
        if (tid < CPB) {
#pragma unroll
            for (int i = 0; i < CHUNK; i++) {
                float dd = sd[i * CPB + tid];       // off-chain LDS
                float w1 = dd - VTH_C;              // off-chain
                v = fmaf(ALPHA_C, v, p ? w1 : dd);  // FSEL + FFMA on chain
                p = (v > VTH_C);                    // FSETP on chain
                sv[tid * PAD + i] = v;              // z recomputed by writers
            }
        }
        __syncthreads();

        // ---- coalesced writeout (all 256 threads) ----
        const int tbase = c * CHUNK;
        float* __restrict__ vo = out + (size_t)b0 * TT + tbase;
        float* __restrict__ zo = vo + (size_t)BB * TT;
#pragma unroll
        for (int k = 0; k < 7; k++) {
            int idx = tid + 256 * k;        // 0..1599
            if (idx < CHUNK * CPB) {
                int bb = idx / CHUNK;
                int ii = idx - bb * CHUNK;
                float vv = sv[bb * PAD + ii];
                vo[(size_t)bb * TT + ii] = vv;
                zo[(size_t)bb * TT + ii] = (vv > VTH_C) ? 1.0f : 0.0f;
            }
        }
        __syncthreads();                    // sd/sv free before next chunk
    }
}

// ---------------------------------------------------------------------------
// fused kernel: blocks [0,SCB) consume, blocks [SCB, TOTAL) produce
// ---------------------------------------------------------------------------
__global__ void __launch_bounds__(256, 3) lif_fused_kernel(
    const float* __restrict__ x, const float* __restrict__ w,
    float* __restrict__ out) {
    if (blockIdx.x < SCB) {
        scan_part(blockIdx.x, out);
    } else {
        gemv_part(x, w);
    }
}

extern "C" void kernel_launch(void* const* d_in, const int* in_sizes, int n_in,
                              void* d_out, int out_size) {
    const float* x = (const float*)d_in[0];   // [B, T, N] f32
    const float* w = (const float*)d_in[1];   // [N] f32
    float* out = (float*)d_out;               // [2, B, T] f32 (v then z)

    lif_poison_kernel<<<125, 256>>>();        // 32000 uint4 = whole g_drive
    lif_fused_kernel<<<TOTAL_BLOCKS, 256>>>(x, w, out);
}

// round 12
// speedup vs baseline: 1.4320x; 1.0279x over previous
#include <cuda_runtime.h>
#include <cstdint>

#define BB 128
#define TT 1000
#define NN 1024
#define ALPHA_C 0.995f
#define VTH_C 2.0f

#define SCB 4                 // scan blocks
#define CPB (BB / SCB)        // chains per scan block = 32
#define CHUNK 50              // timesteps per chunk
#define NCHUNK (TT / CHUNK)   // 20
#define PAD (CHUNK + 1)       // conflict-free staging stride
#define GEMV_BLOCKS 440
#define TOTAL_BLOCKS (GEMV_BLOCKS + SCB)   // 444 = 3/SM * 148 SM, one wave
#define ROWS_PER_CHUNK (BB * CHUNK)        // 6400
#define GRP 4                               // rows per producer step

#define POISON 0x7FBFFFFFu    // NaN bit pattern; drive values are always finite

// drive scratch, block-major: [SCB][TT][CPB]; poisoned before each run
__device__ float g_drive[SCB * TT * CPB];

// ---------------------------------------------------------------------------
// helpers
// ---------------------------------------------------------------------------
__device__ __forceinline__ void stg_cg(float* p, float v) {
    asm volatile("st.global.cg.f32 [%0], %1;" :: "l"(p), "f"(v) : "memory");
}
// streaming load: evict-first in L1 and L2 (x is read exactly once)
__device__ __forceinline__ float4 ldg_cs4(const float4* p) {
    float4 v;
    asm volatile("ld.global.cs.v4.f32 {%0,%1,%2,%3}, [%4];"
                 : "=f"(v.x), "=f"(v.y), "=f"(v.z), "=f"(v.w) : "l"(p));
    return v;
}
// L2-direct async copy: never allocates in L1 -> retry loop always sees fresh L2
__device__ __forceinline__ void cp_async16_cg(void* smem_dst, const void* gmem_src) {
    unsigned saddr = (unsigned)__cvta_generic_to_shared(smem_dst);
    asm volatile("cp.async.cg.shared.global [%0], [%1], 16;\n"
                 :: "r"(saddr), "l"(gmem_src) : "memory");
}
__device__ __forceinline__ void cp_async_commit() {
    asm volatile("cp.async.commit_group;\n" ::: "memory");
}
__device__ __forceinline__ void cp_async_wait0() {
    asm volatile("cp.async.wait_group 0;\n" ::: "memory");
}

// ---------------------------------------------------------------------------
// Kernel 0: poison the drive buffer (every call; ~0.5 MB)
// ---------------------------------------------------------------------------
__global__ void lif_poison_kernel() {
    int i = blockIdx.x * 256 + threadIdx.x;          // 32000 uint4
    ((uint4*)g_drive)[i] = make_uint4(POISON, POISON, POISON, POISON);
}

// ---------------------------------------------------------------------------
// producer: drive[b,t] = dot(x[b,t,:], w) — zero sync overhead.
// Chunk-outer order (pacing), w in regs, MLP=8, x loads evict-first (.cs).
// ---------------------------------------------------------------------------
__device__ void gemv_part(const float* __restrict__ x, const float* __restrict__ w) {
    const int lane  = threadIdx.x & 31;
    const int warp  = ((blockIdx.x - SCB) * blockDim.x + threadIdx.x) >> 5;
    const int nwarp = (GEMV_BLOCKS * 256) >> 5;     // 3520

    const float4* __restrict__ w4 = (const float4*)w;
    float4 wr[8];
#pragma unroll
    for (int k = 0; k < 8; k++) wr[k] = w4[lane + 32 * k];

    const int G = (BB * TT) / GRP;                   // 32000 groups
    for (int g = warp; g < G; g += nwarp) {
        const int q0    = g * GRP;
        const int chunk = q0 / ROWS_PER_CHUNK;
        const int rem0  = q0 - chunk * ROWS_PER_CHUNK;
        const int blk   = rem0 / (CPB * CHUNK);

#pragma unroll
        for (int r = 0; r < GRP; r++) {
            const int rem = rem0 + r;
            const int b   = rem / CHUNK;
            const int t   = chunk * CHUNK + (rem - b * CHUNK);

            const float4* __restrict__ x4 =
                (const float4*)(x + ((size_t)b * TT + t) * NN);
            float s = 0.0f;
#pragma unroll
            for (int k = 0; k < 8; k++) {            // 8 independent LDG.128.CS
                float4 xv = ldg_cs4(&x4[lane + 32 * k]);
                s += xv.x * wr[k].x;
                s += xv.y * wr[k].y;
                s += xv.z * wr[k].z;
                s += xv.w * wr[k].w;
            }
#pragma unroll
            for (int off = 16; off > 0; off >>= 1)
                s += __shfl_xor_sync(0xffffffffu, s, off);
            if (lane == 0)
                stg_cg(&g_drive[blk * (TT * CPB) + t * CPB + (b & 31)], s);
        }
    }
}

// ---------------------------------------------------------------------------
// consumer: LIF scan for 32 chains. Completeness detected from the data:
// fetch chunk via cp.async.cg, verify no POISON words remain, else retry.
// ---------------------------------------------------------------------------
__device__ void scan_part(int blk, float* __restrict__ out) {
    __shared__ float sd[CHUNK * CPB];      // drive staging [t][chain], 6.4 KB
    __shared__ float sv[CPB * PAD];        // v staging [chain][t]

    const int tid = threadIdx.x;           // 0..255
    const int b0  = blk * CPB;
    const float4* __restrict__ gsrc =
        (const float4*)(g_drive + (size_t)blk * TT * CPB);
    const int F4C = CHUNK * CPB / 4;       // 400 float4 per chunk

    float v = 0.0f;
    bool  p = false;

    for (int c = 0; c < NCHUNK; c++) {
        // ---- fetch + verify (retry until producer filled this chunk) ----
        const float4* src = gsrc + c * F4C;
        int done = 0;
        while (!done) {
#pragma unroll
            for (int k = 0; k < 2; k++) {
                int idx = tid + 256 * k;
                if (idx < F4C) cp_async16_cg(&((float4*)sd)[idx], &src[idx]);
            }
            cp_async_commit();
            cp_async_wait0();
            __syncthreads();               // staged data visible to all
            bool ok = true;
#pragma unroll
            for (int k = 0; k < 2; k++) {
                int idx = tid + 256 * k;
                if (idx < F4C) {
                    uint4 u = ((uint4*)sd)[idx];
                    ok &= (u.x != POISON) & (u.y != POISON) &
                          (u.z != POISON) & (u.w != POISON);
                }
            }
            done = __syncthreads_and(ok);
            if (!done) __nanosleep(128);
        }

        // ---- serial chains (one chain per thread, warp 0) ----
        if (tid < CPB) {
#pragma unroll
            for (int i = 0; i < CHUNK; i++) {
                float dd = sd[i * CPB + tid];       // off-chain LDS
                float w1 = dd - VTH_C;              // off-chain
                v = fmaf(ALPHA_C, v, p ? w1 : dd);  // FSEL + FFMA on chain
                p = (v > VTH_C);                    // FSETP on chain
                sv[tid * PAD + i] = v;              // z recomputed by writers
            }
        }
        __syncthreads();

        // ---- coalesced writeout (all 256 threads) ----
        const int tbase = c * CHUNK;
        float* __restrict__ vo = out + (size_t)b0 * TT + tbase;
        float* __restrict__ zo = vo + (size_t)BB * TT;
#pragma unroll
        for (int k = 0; k < 7; k++) {
            int idx = tid + 256 * k;        // 0..1599
            if (idx < CHUNK * CPB) {
                int bb = idx / CHUNK;
                int ii = idx - bb * CHUNK;
                float vv = sv[bb * PAD + ii];
                vo[(size_t)bb * TT + ii] = vv;
                zo[(size_t)bb * TT + ii] = (vv > VTH_C) ? 1.0f : 0.0f;
            }
        }
        __syncthreads();                    // sd/sv free before next chunk
    }
}

// ---------------------------------------------------------------------------
// fused kernel: blocks [0,SCB) consume, blocks [SCB, TOTAL) produce
// ---------------------------------------------------------------------------
__global__ void __launch_bounds__(256, 3) lif_fused_kernel(
    const float* __restrict__ x, const float* __restrict__ w,
    float* __restrict__ out) {
    if (blockIdx.x < SCB) {
        scan_part(blockIdx.x, out);
    } else {
        gemv_part(x, w);
    }
}

extern "C" void kernel_launch(void* const* d_in, const int* in_sizes, int n_in,
                              void* d_out, int out_size) {
    const float* x = (const float*)d_in[0];   // [B, T, N] f32
    const float* w = (const float*)d_in[1];   // [N] f32
    float* out = (float*)d_out;               // [2, B, T] f32 (v then z)

    lif_poison_kernel<<<125, 256>>>();        // 32000 uint4 = whole g_drive
    lif_fused_kernel<<<TOTAL_BLOCKS, 256>>>(x, w, out);
}